// round 15
// baseline (speedup 1.0000x reference)
#include <cuda_runtime.h>
#include <cuda_bf16.h>
#include <cuda_fp16.h>

#define NN 100000
#define EE 1600000
#define DIM 128
#define NH 4
#define HD 32
#define CAP 64                        // bucket capacity; P(Poisson(16) >= 64) ~ 1e-19

// ---------------- device scratch (static — no allocation allowed) ----------------
// g_deg: zero at load (static init); k_agg re-zeroes after reading each execution,
// so graph replays always start from zero.
__device__ uint2 g_hh[(size_t)NN * 32];      // projected features, fp16 [N,128]
__device__ float g_esrc[NN * NH];            // per-node src logits [N,4]
__device__ float g_edst[NN * NH];            // per-node dst logits [N,4]
__device__ int   g_deg[NN];
__device__ int   g_edge_src[(size_t)NN * CAP];  // bucketed CSR: src ids per dst
__device__ int   g_is64;

// ---------------- helpers ----------------
__device__ __forceinline__ int edge_idx(const void* p, int i, int is64) {
    return is64 ? (int)((const long long*)p)[i] : ((const int*)p)[i];
}
__device__ __forceinline__ unsigned pkh2(float a, float b) {
    __half2 h = __floats2half2_rn(a, b);
    return *(unsigned*)&h;
}

// ---------------- dtype detect: 1 warp ----------------
__global__ void k_detect(const void* src) {
    const unsigned* p = (const unsigned*)src;
    int lane = threadIdx.x;
    unsigned hi = p[2 * lane + 1] | p[2 * (lane + 32) + 1];
    unsigned b = __ballot_sync(0xffffffffu, hi == 0u);
    if (lane == 0) g_is64 = (b == 0xffffffffu) ? 1 : 0;
}

// ---------------- CSR build: single pass, fixed-cap buckets ----------------
__global__ void k_build(const void* __restrict__ src, const void* __restrict__ dst) {
    int i = blockIdx.x * blockDim.x + threadIdx.x;
    if (i >= EE) return;
    int is64 = g_is64;
    int d = edge_idx(dst, i, is64);
    int s = edge_idx(src, i, is64);
    int slot = atomicAdd(&g_deg[d], 1);
    if (slot < CAP) g_edge_src[(size_t)d * CAP + slot] = s;
}

// ---------------- GEMM via HMMA (mma.sync m16n8k16, fp16 in / fp32 accum) ----------------
// h = feat @ fc_w.T. Block: 128 rows x 128 cols x K=128.
// fc_w staged in smem as fp16 [n][k] padded; A-fragments loaded straight from gmem.
// Warp w computes rows [w*16, w*16+16) x all 128 cols -> fused logits stay in-warp.
#define SBK 136                       // padded k-extent (halves): row stride 272B
__global__ void __launch_bounds__(256) k_gemm(const float* __restrict__ feat,
                                              const float* __restrict__ fc_w,
                                              const float* __restrict__ attn_src,
                                              const float* __restrict__ attn_dst) {
    __shared__ __half sB[128][SBK];
    __shared__ float s_as[DIM], s_ad[DIM];
    int tid = threadIdx.x;
    int lane = tid & 31;
    int wm = tid >> 5;                // warp id 0..7 -> row strip
    int g = lane >> 2;                // 0..7
    int tig = lane & 3;               // 0..3
    int rbase = blockIdx.x * 128;

    // stage fc_w -> sB (fp16): 128 rows x 128 cols = 2048 ids x 8 floats
#pragma unroll
    for (int q = 0; q < 8; q++) {
        int id = tid + q * 256;       // 0..2047
        int n = id >> 4;              // 0..127
        int c = (id & 15) * 8;        // 0..120 step 8
        float4 v0 = *(const float4*)&fc_w[n * DIM + c];
        float4 v1 = *(const float4*)&fc_w[n * DIM + c + 4];
        unsigned* d = (unsigned*)&sB[n][c];
        d[0] = pkh2(v0.x, v0.y); d[1] = pkh2(v0.z, v0.w);
        d[2] = pkh2(v1.x, v1.y); d[3] = pkh2(v1.z, v1.w);
    }
    if (tid < DIM) { s_as[tid] = attn_src[tid]; s_ad[tid] = attn_dst[tid]; }
    __syncthreads();

    int r0 = rbase + wm * 16 + g;
    int r1 = r0 + 8;
    int ra = r0 < NN ? r0 : NN - 1;   // clamped addresses for loads
    int rb = r1 < NN ? r1 : NN - 1;
    const float* pa = feat + (size_t)ra * DIM;
    const float* pb = feat + (size_t)rb * DIM;

    float c0[16], c1[16], c2[16], c3[16];
#pragma unroll
    for (int ni = 0; ni < 16; ni++) { c0[ni] = 0.f; c1[ni] = 0.f; c2[ni] = 0.f; c3[ni] = 0.f; }

    unsigned A[2][4];
    {   // preload k-step 0
        int kk = 2 * tig;
        float2 v0 = *(const float2*)&pa[kk];
        float2 v1 = *(const float2*)&pb[kk];
        float2 v2 = *(const float2*)&pa[kk + 8];
        float2 v3 = *(const float2*)&pb[kk + 8];
        A[0][0] = pkh2(v0.x, v0.y); A[0][1] = pkh2(v1.x, v1.y);
        A[0][2] = pkh2(v2.x, v2.y); A[0][3] = pkh2(v3.x, v3.y);
    }

#pragma unroll
    for (int k = 0; k < 8; k++) {
        int cur = k & 1, nxt = cur ^ 1;
        if (k < 7) {
            int kk = (k + 1) * 16 + 2 * tig;
            float2 v0 = *(const float2*)&pa[kk];
            float2 v1 = *(const float2*)&pb[kk];
            float2 v2 = *(const float2*)&pa[kk + 8];
            float2 v3 = *(const float2*)&pb[kk + 8];
            A[nxt][0] = pkh2(v0.x, v0.y); A[nxt][1] = pkh2(v1.x, v1.y);
            A[nxt][2] = pkh2(v2.x, v2.y); A[nxt][3] = pkh2(v3.x, v3.y);
        }
        int kb = k * 16 + 2 * tig;
#pragma unroll
        for (int ni = 0; ni < 16; ni++) {
            unsigned b0 = *(const unsigned*)&sB[ni * 8 + g][kb];
            unsigned b1 = *(const unsigned*)&sB[ni * 8 + g][kb + 8];
            asm("mma.sync.aligned.m16n8k16.row.col.f32.f16.f16.f32 "
                "{%0,%1,%2,%3}, {%4,%5,%6,%7}, {%8,%9}, {%0,%1,%2,%3};"
                : "+f"(c0[ni]), "+f"(c1[ni]), "+f"(c2[ni]), "+f"(c3[ni])
                : "r"(A[cur][0]), "r"(A[cur][1]), "r"(A[cur][2]), "r"(A[cur][3]),
                  "r"(b0), "r"(b1));
        }
    }

    // ---- epilogue: store fp16 h + fused per-head logits ----
    unsigned* hu = (unsigned*)g_hh;   // [node][64] half2 view
    float ps0[NH] = {0, 0, 0, 0}, pd0[NH] = {0, 0, 0, 0};
    float ps1[NH] = {0, 0, 0, 0}, pd1[NH] = {0, 0, 0, 0};
#pragma unroll
    for (int ni = 0; ni < 16; ni++) {
        int n0 = ni * 8 + 2 * tig;
        int h = ni >> 2;
        float asx = s_as[n0], asy = s_as[n0 + 1];
        float adx = s_ad[n0], ady = s_ad[n0 + 1];
        ps0[h] += c0[ni] * asx + c1[ni] * asy;
        pd0[h] += c0[ni] * adx + c1[ni] * ady;
        ps1[h] += c2[ni] * asx + c3[ni] * asy;
        pd1[h] += c2[ni] * adx + c3[ni] * ady;
        if (r0 < NN) hu[(size_t)r0 * 64 + ni * 4 + tig] = pkh2(c0[ni], c1[ni]);
        if (r1 < NN) hu[(size_t)r1 * 64 + ni * 4 + tig] = pkh2(c2[ni], c3[ni]);
    }
#pragma unroll
    for (int o = 1; o < 4; o <<= 1) {
#pragma unroll
        for (int h = 0; h < NH; h++) {
            ps0[h] += __shfl_xor_sync(0xffffffffu, ps0[h], o);
            pd0[h] += __shfl_xor_sync(0xffffffffu, pd0[h], o);
            ps1[h] += __shfl_xor_sync(0xffffffffu, ps1[h], o);
            pd1[h] += __shfl_xor_sync(0xffffffffu, pd1[h], o);
        }
    }
    if (tig == 0) {
#pragma unroll
        for (int h = 0; h < NH; h++) {
            if (r0 < NN) { g_esrc[r0 * NH + h] = ps0[h]; g_edst[r0 * NH + h] = pd0[h]; }
            if (r1 < NN) { g_esrc[r1 * NH + h] = ps1[h]; g_edst[r1 * NH + h] = pd1[h]; }
        }
    }
}

// ---------------- softmax + aggregation: warp per dst node, single pass ----------------
__global__ void __launch_bounds__(256) k_agg(const float* __restrict__ feat,
                                             float* __restrict__ out) {
    int n = (blockIdx.x * blockDim.x + threadIdx.x) >> 5;
    int lane = threadIdx.x & 31;
    if (n >= NN) return;
    int deg = g_deg[n];
    if (lane == 0) g_deg[n] = 0;      // reset for next graph replay (last reader)
    deg = deg < CAP ? deg : CAP;
    float4 f4 = *(const float4*)&feat[(size_t)n * DIM + lane * 4];
    if (deg == 0) {                   // no incoming edges: out = feat (residual)
        *(float4*)&out[(size_t)n * DIM + lane * 4] = f4;
        return;
    }
    int head = lane >> 3;             // this lane's 4 dims belong to one head
    float edh = g_edst[n * NH + head];

    const uint2* hh = g_hh;
    const int* ebase = &g_edge_src[(size_t)n * CAP];   // 16B-aligned bucket
    float ssum = 0.f;
    float4 acc = make_float4(0.f, 0.f, 0.f, 0.f);

    int i = 0;
    for (; i + 4 <= deg; i += 4) {
        int4 sv = *(const int4*)&ebase[i];             // aligned vector load
        int s0 = sv.x, s1 = sv.y, s2 = sv.z, s3 = sv.w;
        float e0 = g_esrc[s0 * NH + head] + edh;
        float e1 = g_esrc[s1 * NH + head] + edh;
        float e2 = g_esrc[s2 * NH + head] + edh;
        float e3 = g_esrc[s3 * NH + head] + edh;
        uint2 u0 = hh[(size_t)s0 * 32 + lane];
        uint2 u1 = hh[(size_t)s1 * 32 + lane];
        uint2 u2 = hh[(size_t)s2 * 32 + lane];
        uint2 u3 = hh[(size_t)s3 * 32 + lane];
        e0 = e0 > 0.f ? e0 : 0.2f * e0;
        e1 = e1 > 0.f ? e1 : 0.2f * e1;
        e2 = e2 > 0.f ? e2 : 0.2f * e2;
        e3 = e3 > 0.f ? e3 : 0.2f * e3;
        float w0 = __expf(e0);
        float w1 = __expf(e1);
        float w2 = __expf(e2);
        float w3 = __expf(e3);
        ssum += (w0 + w1) + (w2 + w3);
        float2 a0 = __half22float2(*(const __half2*)&u0.x);
        float2 b0 = __half22float2(*(const __half2*)&u0.y);
        float2 a1 = __half22float2(*(const __half2*)&u1.x);
        float2 b1 = __half22float2(*(const __half2*)&u1.y);
        float2 a2 = __half22float2(*(const __half2*)&u2.x);
        float2 b2 = __half22float2(*(const __half2*)&u2.y);
        float2 a3 = __half22float2(*(const __half2*)&u3.x);
        float2 b3 = __half22float2(*(const __half2*)&u3.y);
        acc.x += w0 * a0.x; acc.y += w0 * a0.y;
        acc.z += w0 * b0.x; acc.w += w0 * b0.y;
        acc.x += w1 * a1.x; acc.y += w1 * a1.y;
        acc.z += w1 * b1.x; acc.w += w1 * b1.y;
        acc.x += w2 * a2.x; acc.y += w2 * a2.y;
        acc.z += w2 * b2.x; acc.w += w2 * b2.y;
        acc.x += w3 * a3.x; acc.y += w3 * a3.y;
        acc.z += w3 * b3.x; acc.w += w3 * b3.y;
    }
    for (; i < deg; i++) {
        int s = ebase[i];
        float e = g_esrc[s * NH + head] + edh;
        uint2 u = hh[(size_t)s * 32 + lane];
        e = e > 0.f ? e : 0.2f * e;
        float w = __expf(e);
        ssum += w;
        float2 a = __half22float2(*(const __half2*)&u.x);
        float2 b = __half22float2(*(const __half2*)&u.y);
        acc.x += w * a.x; acc.y += w * a.y;
        acc.z += w * b.x; acc.w += w * b.y;
    }
    float inv = 1.0f / ssum;          // ssum > 0 guaranteed (deg >= 1, exp > 0)
    float4 o4;
    o4.x = acc.x * inv + f4.x;
    o4.y = acc.y * inv + f4.y;
    o4.z = acc.z * inv + f4.z;
    o4.w = acc.w * inv + f4.w;
    *(float4*)&out[(size_t)n * DIM + lane * 4] = o4;
}

// ---------------- launch ----------------
extern "C" void kernel_launch(void* const* d_in, const int* in_sizes, int n_in,
                              void* d_out, int out_size) {
    const float* feat     = (const float*)d_in[0];
    const float* fc_w     = (const float*)d_in[1];
    const float* attn_src = (const float*)d_in[2];
    const float* attn_dst = (const float*)d_in[3];
    const void*  src      = d_in[4];
    const void*  dst      = d_in[5];
    float* out = (float*)d_out;

    static cudaStream_t s2 = nullptr;
    static cudaEvent_t evA = nullptr, evB = nullptr;
    if (!s2) {
        cudaStreamCreate(&s2);
        cudaEventCreateWithFlags(&evA, cudaEventDisableTiming);
        cudaEventCreateWithFlags(&evB, cudaEventDisableTiming);
    }

    // fork: CSR bucket build on s2 (depends only on src/dst), GEMM on main stream
    cudaEventRecord(evA, 0);
    cudaStreamWaitEvent(s2, evA, 0);

    k_detect<<<1, 32, 0, s2>>>(src);
    k_build<<<(EE + 255) / 256, 256, 0, s2>>>(src, dst);
    cudaEventRecord(evB, s2);

    k_gemm<<<(NN + 127) / 128, 256>>>(feat, fc_w, attn_src, attn_dst);

    // join, then aggregate
    cudaStreamWaitEvent(0, evB, 0);
    k_agg<<<(NN + 7) / 8, 256>>>(feat, out);
}

// round 17
// speedup vs baseline: 1.7750x; 1.7750x over previous
#include <cuda_runtime.h>
#include <cuda_bf16.h>
#include <cuda_fp16.h>

#define NN 100000
#define EE 1600000
#define DIM 128
#define NH 4
#define HD 32
#define EHALF (EE / 2)

#define SCAN_B 512
#define SCAN_NB ((NN + SCAN_B - 1) / SCAN_B)   // 196

// ---------------- device scratch (static — no allocation allowed) ----------------
// NOTE: g_deg relies on static zero-init for the first run and is re-zeroed by
// k_scan3 on every execution (after its last read), keeping graph replays correct.
__device__ uint2 g_hh[(size_t)NN * 32];      // projected features, fp16 [N,128]
__device__ float g_esrc[NN * NH];            // per-node src logits [N,4]
__device__ float g_edst[NN * NH];            // per-node dst logits [N,4]
__device__ int   g_deg[NN];
__device__ int   g_off[NN + 1];
__device__ int   g_part[SCAN_NB];            // per-block partial sums
__device__ int   g_partx[SCAN_NB];           // exclusive-scanned partials
__device__ int   g_pos[EE];                  // packed (dst << 10) | slot per edge
__device__ int   g_edge_src[EE];             // src ids grouped by dst (CSR)
__device__ int   g_is64;

// ---------------- helpers ----------------
__device__ __forceinline__ int edge_idx(const void* p, int i, int is64) {
    return is64 ? (int)((const long long*)p)[i] : ((const int*)p)[i];
}
__device__ __forceinline__ unsigned pkh2(float a, float b) {
    __half2 h = __floats2half2_rn(a, b);
    return *(unsigned*)&h;
}

// ---------------- dtype detect: 1 warp ----------------
__global__ void k_detect(const void* src) {
    const unsigned* p = (const unsigned*)src;
    int lane = threadIdx.x;
    unsigned hi = p[2 * lane + 1] | p[2 * (lane + 32) + 1];
    unsigned b = __ballot_sync(0xffffffffu, hi == 0u);
    if (lane == 0) g_is64 = (b == 0xffffffffu) ? 1 : 0;
}

// ---------------- GEMM via HMMA (mma.sync m16n8k16, fp16 in / fp32 accum) ----------------
// h = feat @ fc_w.T. Block: 128 rows x 128 cols x K=128.
// fc_w staged in smem as fp16 [n][k] padded; A-fragments loaded straight from gmem.
// Warp w computes rows [w*16, w*16+16) x all 128 cols -> fused logits stay in-warp.
#define SBK 136                       // padded k-extent (halves): row stride 272B
__global__ void __launch_bounds__(256) k_gemm(const float* __restrict__ feat,
                                              const float* __restrict__ fc_w,
                                              const float* __restrict__ attn_src,
                                              const float* __restrict__ attn_dst) {
    __shared__ __half sB[128][SBK];
    __shared__ float s_as[DIM], s_ad[DIM];
    int tid = threadIdx.x;
    int lane = tid & 31;
    int wm = tid >> 5;                // warp id 0..7 -> row strip
    int g = lane >> 2;                // 0..7
    int tig = lane & 3;               // 0..3
    int rbase = blockIdx.x * 128;

    // stage fc_w -> sB (fp16): 128 rows x 128 cols = 2048 ids x 8 floats
#pragma unroll
    for (int q = 0; q < 8; q++) {
        int id = tid + q * 256;       // 0..2047
        int n = id >> 4;              // 0..127
        int c = (id & 15) * 8;        // 0..120 step 8
        float4 v0 = *(const float4*)&fc_w[n * DIM + c];
        float4 v1 = *(const float4*)&fc_w[n * DIM + c + 4];
        unsigned* d = (unsigned*)&sB[n][c];
        d[0] = pkh2(v0.x, v0.y); d[1] = pkh2(v0.z, v0.w);
        d[2] = pkh2(v1.x, v1.y); d[3] = pkh2(v1.z, v1.w);
    }
    if (tid < DIM) { s_as[tid] = attn_src[tid]; s_ad[tid] = attn_dst[tid]; }
    __syncthreads();

    int r0 = rbase + wm * 16 + g;
    int r1 = r0 + 8;
    int ra = r0 < NN ? r0 : NN - 1;   // clamped addresses for loads
    int rb = r1 < NN ? r1 : NN - 1;
    const float* pa = feat + (size_t)ra * DIM;
    const float* pb = feat + (size_t)rb * DIM;

    float c0[16], c1[16], c2[16], c3[16];
#pragma unroll
    for (int ni = 0; ni < 16; ni++) { c0[ni] = 0.f; c1[ni] = 0.f; c2[ni] = 0.f; c3[ni] = 0.f; }

    unsigned A[2][4];
    {   // preload k-step 0
        int kk = 2 * tig;
        float2 v0 = *(const float2*)&pa[kk];
        float2 v1 = *(const float2*)&pb[kk];
        float2 v2 = *(const float2*)&pa[kk + 8];
        float2 v3 = *(const float2*)&pb[kk + 8];
        A[0][0] = pkh2(v0.x, v0.y); A[0][1] = pkh2(v1.x, v1.y);
        A[0][2] = pkh2(v2.x, v2.y); A[0][3] = pkh2(v3.x, v3.y);
    }

#pragma unroll
    for (int k = 0; k < 8; k++) {
        int cur = k & 1, nxt = cur ^ 1;
        if (k < 7) {
            int kk = (k + 1) * 16 + 2 * tig;
            float2 v0 = *(const float2*)&pa[kk];
            float2 v1 = *(const float2*)&pb[kk];
            float2 v2 = *(const float2*)&pa[kk + 8];
            float2 v3 = *(const float2*)&pb[kk + 8];
            A[nxt][0] = pkh2(v0.x, v0.y); A[nxt][1] = pkh2(v1.x, v1.y);
            A[nxt][2] = pkh2(v2.x, v2.y); A[nxt][3] = pkh2(v3.x, v3.y);
        }
        int kb = k * 16 + 2 * tig;
#pragma unroll
        for (int ni = 0; ni < 16; ni++) {
            unsigned b0 = *(const unsigned*)&sB[ni * 8 + g][kb];
            unsigned b1 = *(const unsigned*)&sB[ni * 8 + g][kb + 8];
            asm("mma.sync.aligned.m16n8k16.row.col.f32.f16.f16.f32 "
                "{%0,%1,%2,%3}, {%4,%5,%6,%7}, {%8,%9}, {%0,%1,%2,%3};"
                : "+f"(c0[ni]), "+f"(c1[ni]), "+f"(c2[ni]), "+f"(c3[ni])
                : "r"(A[cur][0]), "r"(A[cur][1]), "r"(A[cur][2]), "r"(A[cur][3]),
                  "r"(b0), "r"(b1));
        }
    }

    // ---- epilogue: store fp16 h + fused per-head logits ----
    unsigned* hu = (unsigned*)g_hh;   // [node][64] half2 view
    float ps0[NH] = {0, 0, 0, 0}, pd0[NH] = {0, 0, 0, 0};
    float ps1[NH] = {0, 0, 0, 0}, pd1[NH] = {0, 0, 0, 0};
#pragma unroll
    for (int ni = 0; ni < 16; ni++) {
        int n0 = ni * 8 + 2 * tig;
        int h = ni >> 2;
        float asx = s_as[n0], asy = s_as[n0 + 1];
        float adx = s_ad[n0], ady = s_ad[n0 + 1];
        ps0[h] += c0[ni] * asx + c1[ni] * asy;
        pd0[h] += c0[ni] * adx + c1[ni] * ady;
        ps1[h] += c2[ni] * asx + c3[ni] * asy;
        pd1[h] += c2[ni] * adx + c3[ni] * ady;
        if (r0 < NN) hu[(size_t)r0 * 64 + ni * 4 + tig] = pkh2(c0[ni], c1[ni]);
        if (r1 < NN) hu[(size_t)r1 * 64 + ni * 4 + tig] = pkh2(c2[ni], c3[ni]);
    }
#pragma unroll
    for (int o = 1; o < 4; o <<= 1) {
#pragma unroll
        for (int h = 0; h < NH; h++) {
            ps0[h] += __shfl_xor_sync(0xffffffffu, ps0[h], o);
            pd0[h] += __shfl_xor_sync(0xffffffffu, pd0[h], o);
            ps1[h] += __shfl_xor_sync(0xffffffffu, ps1[h], o);
            pd1[h] += __shfl_xor_sync(0xffffffffu, pd1[h], o);
        }
    }
    if (tig == 0) {
#pragma unroll
        for (int h = 0; h < NH; h++) {
            if (r0 < NN) { g_esrc[r0 * NH + h] = ps0[h]; g_edst[r0 * NH + h] = pd0[h]; }
            if (r1 < NN) { g_esrc[r1 * NH + h] = ps1[h]; g_edst[r1 * NH + h] = pd1[h]; }
        }
    }
}

// ---------------- CSR build ----------------
// histogram + record packed (dst, slot) per edge; slot < 1024 (deg ~ Poisson(16))
__global__ void k_hist(const void* __restrict__ dst) {
    int i = blockIdx.x * blockDim.x + threadIdx.x;
    if (i >= EE) return;
    int d = edge_idx(dst, i, g_is64);
    int slot = atomicAdd(&g_deg[d], 1);
    g_pos[i] = (d << 10) | slot;
}

// stage 1: per-block sums of g_deg
__global__ void __launch_bounds__(SCAN_B) k_scan1() {
    __shared__ int sm[SCAN_B];
    int t = threadIdx.x;
    int i = blockIdx.x * SCAN_B + t;
    sm[t] = (i < NN) ? g_deg[i] : 0;
    __syncthreads();
#pragma unroll
    for (int off = SCAN_B / 2; off > 0; off >>= 1) {
        if (t < off) sm[t] += sm[t + off];
        __syncthreads();
    }
    if (t == 0) g_part[blockIdx.x] = sm[0];
}

// stage 2: exclusive scan of SCAN_NB partials (one block)
__global__ void __launch_bounds__(256) k_scan2() {
    __shared__ int sm[256];
    int t = threadIdx.x;
    int v = (t < SCAN_NB) ? g_part[t] : 0;
    sm[t] = v;
    __syncthreads();
#pragma unroll
    for (int off = 1; off < 256; off <<= 1) {
        int x = (t >= off) ? sm[t - off] : 0;
        __syncthreads();
        sm[t] += x;
        __syncthreads();
    }
    if (t < SCAN_NB) g_partx[t] = sm[t] - v;   // exclusive
    if (t == 255) g_off[NN] = sm[255];          // total
}

// stage 3: per-block local scan + global offset -> g_off; re-zero g_deg for next replay
__global__ void __launch_bounds__(SCAN_B) k_scan3() {
    __shared__ int sm[SCAN_B];
    int t = threadIdx.x;
    int i = blockIdx.x * SCAN_B + t;
    int v = (i < NN) ? g_deg[i] : 0;
    sm[t] = v;
    __syncthreads();
#pragma unroll
    for (int off = 1; off < SCAN_B; off <<= 1) {
        int x = (t >= off) ? sm[t - off] : 0;
        __syncthreads();
        sm[t] += x;
        __syncthreads();
    }
    if (i < NN) {
        g_off[i] = g_partx[blockIdx.x] + sm[t] - v;   // exclusive
        g_deg[i] = 0;                                  // reset for next graph replay
    }
}

// scatter a range of edges: no atomics, no dst re-read — (dst, slot) packed in g_pos.
// Halves write disjoint g_edge_src slots, so splitting across streams is race-free.
__global__ void k_scatter(const void* __restrict__ src, int base, int count) {
    int i = blockIdx.x * blockDim.x + threadIdx.x;
    if (i >= count) return;
    i += base;
    int s = edge_idx(src, i, g_is64);
    int pk = g_pos[i];
    g_edge_src[g_off[pk >> 10] + (pk & 1023)] = s;
}

// ---------------- softmax + aggregation: warp per dst node, single pass ----------------
__global__ void __launch_bounds__(256) k_agg(const float* __restrict__ feat,
                                             float* __restrict__ out) {
    int n = (blockIdx.x * blockDim.x + threadIdx.x) >> 5;
    int lane = threadIdx.x & 31;
    if (n >= NN) return;
    int beg = g_off[n], end = g_off[n + 1];
    float4 f4 = *(const float4*)&feat[(size_t)n * DIM + lane * 4];
    if (beg == end) {                 // no incoming edges: out = feat (residual)
        *(float4*)&out[(size_t)n * DIM + lane * 4] = f4;
        return;
    }
    int head = lane >> 3;             // this lane's 4 dims belong to one head
    float edh = g_edst[n * NH + head];

    const uint2* hh = g_hh;
    float ssum = 0.f;
    float4 acc = make_float4(0.f, 0.f, 0.f, 0.f);

    int i = beg;
    for (; i + 4 <= end; i += 4) {
        int s0 = g_edge_src[i];
        int s1 = g_edge_src[i + 1];
        int s2 = g_edge_src[i + 2];
        int s3 = g_edge_src[i + 3];
        float e0 = g_esrc[s0 * NH + head] + edh;
        float e1 = g_esrc[s1 * NH + head] + edh;
        float e2 = g_esrc[s2 * NH + head] + edh;
        float e3 = g_esrc[s3 * NH + head] + edh;
        uint2 u0 = hh[(size_t)s0 * 32 + lane];
        uint2 u1 = hh[(size_t)s1 * 32 + lane];
        uint2 u2 = hh[(size_t)s2 * 32 + lane];
        uint2 u3 = hh[(size_t)s3 * 32 + lane];
        e0 = e0 > 0.f ? e0 : 0.2f * e0;
        e1 = e1 > 0.f ? e1 : 0.2f * e1;
        e2 = e2 > 0.f ? e2 : 0.2f * e2;
        e3 = e3 > 0.f ? e3 : 0.2f * e3;
        float w0 = __expf(e0);
        float w1 = __expf(e1);
        float w2 = __expf(e2);
        float w3 = __expf(e3);
        ssum += (w0 + w1) + (w2 + w3);
        float2 a0 = __half22float2(*(const __half2*)&u0.x);
        float2 b0 = __half22float2(*(const __half2*)&u0.y);
        float2 a1 = __half22float2(*(const __half2*)&u1.x);
        float2 b1 = __half22float2(*(const __half2*)&u1.y);
        float2 a2 = __half22float2(*(const __half2*)&u2.x);
        float2 b2 = __half22float2(*(const __half2*)&u2.y);
        float2 a3 = __half22float2(*(const __half2*)&u3.x);
        float2 b3 = __half22float2(*(const __half2*)&u3.y);
        acc.x += w0 * a0.x; acc.y += w0 * a0.y;
        acc.z += w0 * b0.x; acc.w += w0 * b0.y;
        acc.x += w1 * a1.x; acc.y += w1 * a1.y;
        acc.z += w1 * b1.x; acc.w += w1 * b1.y;
        acc.x += w2 * a2.x; acc.y += w2 * a2.y;
        acc.z += w2 * b2.x; acc.w += w2 * b2.y;
        acc.x += w3 * a3.x; acc.y += w3 * a3.y;
        acc.z += w3 * b3.x; acc.w += w3 * b3.y;
    }
    for (; i < end; i++) {
        int s = g_edge_src[i];
        float e = g_esrc[s * NH + head] + edh;
        uint2 u = hh[(size_t)s * 32 + lane];
        e = e > 0.f ? e : 0.2f * e;
        float w = __expf(e);
        ssum += w;
        float2 a = __half22float2(*(const __half2*)&u.x);
        float2 b = __half22float2(*(const __half2*)&u.y);
        acc.x += w * a.x; acc.y += w * a.y;
        acc.z += w * b.x; acc.w += w * b.y;
    }
    float inv = 1.0f / ssum;          // ssum > 0 guaranteed (deg >= 1, exp > 0)
    float4 o4;
    o4.x = acc.x * inv + f4.x;
    o4.y = acc.y * inv + f4.y;
    o4.z = acc.z * inv + f4.z;
    o4.w = acc.w * inv + f4.w;
    *(float4*)&out[(size_t)n * DIM + lane * 4] = o4;
}

// ---------------- launch ----------------
extern "C" void kernel_launch(void* const* d_in, const int* in_sizes, int n_in,
                              void* d_out, int out_size) {
    const float* feat     = (const float*)d_in[0];
    const float* fc_w     = (const float*)d_in[1];
    const float* attn_src = (const float*)d_in[2];
    const float* attn_dst = (const float*)d_in[3];
    const void*  src      = d_in[4];
    const void*  dst      = d_in[5];
    float* out = (float*)d_out;

    static cudaStream_t s2 = nullptr;
    static cudaEvent_t evA = nullptr, evB = nullptr, evC = nullptr;
    if (!s2) {
        cudaStreamCreate(&s2);
        cudaEventCreateWithFlags(&evA, cudaEventDisableTiming);
        cudaEventCreateWithFlags(&evB, cudaEventDisableTiming);
        cudaEventCreateWithFlags(&evC, cudaEventDisableTiming);
    }

    // fork: CSR chain on s2 (depends only on src/dst), GEMM on main stream
    cudaEventRecord(evA, 0);
    cudaStreamWaitEvent(s2, evA, 0);

    k_detect<<<1, 32, 0, s2>>>(src);
    k_hist<<<(EE + 255) / 256, 256, 0, s2>>>(dst);
    k_scan1<<<SCAN_NB, SCAN_B, 0, s2>>>();
    k_scan2<<<1, 256, 0, s2>>>();
    k_scan3<<<SCAN_NB, SCAN_B, 0, s2>>>();
    cudaEventRecord(evC, s2);                         // g_pos + g_off ready
    // second half of scatter stays on s2
    k_scatter<<<(EE - EHALF + 255) / 256, 256, 0, s2>>>(src, EHALF, EE - EHALF);
    cudaEventRecord(evB, s2);

    // main: GEMM, then pick up the first scatter half once offsets are ready
    k_gemm<<<(NN + 127) / 128, 256>>>(feat, fc_w, attn_src, attn_dst);
    cudaStreamWaitEvent(0, evC, 0);
    k_scatter<<<(EHALF + 255) / 256, 256>>>(src, 0, EHALF);

    // join, then aggregate
    cudaStreamWaitEvent(0, evB, 0);
    k_agg<<<(NN + 7) / 8, 256>>>(feat, out);
}